// round 15
// baseline (speedup 1.0000x reference)
#include <cuda_runtime.h>
#include <cuda_bf16.h>
#include <stdint.h>

#define B_ROWS   4096
#define D_MODEL  768
#define DICT     24576
#define K_TOP    64
#define CAND_CAP 512
#define MARGIN   0.05f
#define NTILE    (DICT / 128)     // 192

// ---------------- scratch (device globals) ----------------
__device__ __nv_bfloat16 g_xb[(size_t)B_ROWS * D_MODEL];
__device__ __nv_bfloat16 g_wb[(size_t)DICT * D_MODEL];
__device__ __nv_bfloat16 g_preh[(size_t)B_ROWS * DICT];
__device__ float g_tilemax[(size_t)B_ROWS * NTILE];
__device__ float g_wdt[(size_t)DICT * D_MODEL];
__device__ int   g_idx[(size_t)B_ROWS * K_TOP];
__device__ float g_val[(size_t)B_ROWS * K_TOP];

__device__ __forceinline__ uint32_t smem_u32(const void* p) {
    uint32_t a;
    asm("{ .reg .u64 t; cvta.to.shared.u64 t, %1; cvt.u32.u64 %0, t; }" : "=r"(a) : "l"(p));
    return a;
}

// ---------------- K0: fused prep = zero_acts + converts + transpose ----------
#define ZBLK   4096
#define CVT4   ((B_ROWS * D_MODEL + DICT * D_MODEL) / 4)
#define CBLK   ((CVT4 + 255) / 256)
#define TBLK   ((DICT / 32) * (D_MODEL / 32))

__global__ __launch_bounds__(256)
void prep_kernel(const float* __restrict__ x,
                 const float* __restrict__ wenc,
                 const float* __restrict__ wdec,
                 float* __restrict__ acts_out) {
    const int tid = threadIdx.x;
    unsigned b = blockIdx.x;

    if (b < ZBLK) {
        float* arow = acts_out + (size_t)b * DICT;
        float4 z = make_float4(0.f, 0.f, 0.f, 0.f);
#pragma unroll
        for (int i = 0; i < DICT / 4 / 256; i++)
            ((float4*)arow)[tid + i * 256] = z;
        return;
    }
    b -= ZBLK;

    if (b < (unsigned)CBLK) {
        const int nx4 = B_ROWS * D_MODEL / 4;
        int i = b * 256 + tid;
        if (i < nx4) {
            float4 v = ((const float4*)x)[i];
            __nv_bfloat162* o = (__nv_bfloat162*)g_xb;
            o[2 * i]     = __floats2bfloat162_rn(v.x, v.y);
            o[2 * i + 1] = __floats2bfloat162_rn(v.z, v.w);
        } else if (i < CVT4) {
            int j = i - nx4;
            float4 v = ((const float4*)wenc)[j];
            __nv_bfloat162* o = (__nv_bfloat162*)g_wb;
            o[2 * j]     = __floats2bfloat162_rn(v.x, v.y);
            o[2 * j + 1] = __floats2bfloat162_rn(v.z, v.w);
        }
        return;
    }
    b -= CBLK;

    {
        __shared__ float s[32][33];
        const int f0 = (b % (DICT / 32)) * 32;
        const int d0 = (b / (DICT / 32)) * 32;
        const int tx = tid & 31, ty = tid >> 5;
#pragma unroll
        for (int i = 0; i < 4; i++)
            s[ty + i * 8][tx] = wdec[(size_t)(d0 + ty + i * 8) * DICT + f0 + tx];
        __syncthreads();
#pragma unroll
        for (int i = 0; i < 4; i++)
            g_wdt[(size_t)(f0 + ty + i * 8) * D_MODEL + d0 + tx] = s[tx][ty + i * 8];
    }
}

// ---------------- K1: bf16 mma GEMM, 5-stage pipeline, 1 barrier/chunk -------
#define PITCH 40
#define KCH   32
#define NCHUNKS (D_MODEL / KCH)            // 24
#define STAGE_BYTES (128 * PITCH * 2)      // 10240
#define NSTAGE 5
#define GEMM_SMEM (2 * NSTAGE * STAGE_BYTES)   // 102400

__device__ __forceinline__ void cp16(uint32_t saddr, const void* g) {
    asm volatile("cp.async.ca.shared.global [%0], [%1], 16;" :: "r"(saddr), "l"(g));
}

__global__ __launch_bounds__(128, 2)
void gemm_enc_mma(const float* __restrict__ benc) {
    extern __shared__ __align__(128) char dsm[];
    __shared__ float s_bias[128];
    __shared__ float s_tm[128][2];

    const int tid  = threadIdx.x;
    const int wid  = tid >> 5;
    const int lane = tid & 31;
    const int wm   = wid & 1;
    const int wn   = wid >> 1;
    const int m0 = blockIdx.y * 128;
    const int n0 = blockIdx.x * 128;

    if (tid < 128) s_bias[tid] = benc[n0 + tid];

    const __nv_bfloat16* Ag = g_xb + (size_t)m0 * D_MODEL;
    const __nv_bfloat16* Bg = g_wb + (size_t)n0 * D_MODEL;

    const uint32_t sA0 = smem_u32(dsm);
    const uint32_t sB0 = sA0 + NSTAGE * STAGE_BYTES;

    auto issue = [&](int ch, int stg) {
#pragma unroll
        for (int i = 0; i < 4; i++) {
            int seg = tid + (i << 7);
            int r = seg >> 2, c = seg & 3;
            uint32_t so = (uint32_t)stg * STAGE_BYTES + (uint32_t)(r * PITCH + c * 8) * 2u;
            cp16(sA0 + so, Ag + (size_t)r * D_MODEL + ch * KCH + c * 8);
            cp16(sB0 + so, Bg + (size_t)r * D_MODEL + ch * KCH + c * 8);
        }
        asm volatile("cp.async.commit_group;" ::: "memory");
    };

    float c[4][8][4];
#pragma unroll
    for (int i = 0; i < 4; i++)
#pragma unroll
        for (int j = 0; j < 8; j++)
#pragma unroll
            for (int q = 0; q < 4; q++) c[i][j][q] = 0.f;

    issue(0, 0);
    issue(1, 1);
    issue(2, 2);
    issue(3, 3);

#pragma unroll 1
    for (int ch = 0; ch < NCHUNKS; ch++) {
        if (ch + 3 < NCHUNKS)
            asm volatile("cp.async.wait_group 3;" ::: "memory");
        else if (ch + 2 < NCHUNKS)
            asm volatile("cp.async.wait_group 2;" ::: "memory");
        else if (ch + 1 < NCHUNKS)
            asm volatile("cp.async.wait_group 1;" ::: "memory");
        else
            asm volatile("cp.async.wait_group 0;" ::: "memory");
        __syncthreads();
        if (ch + 4 < NCHUNKS) issue(ch + 4, (ch + 4) % NSTAGE);

        const int stg = ch % NSTAGE;
        const uint32_t aS = sA0 + (uint32_t)stg * STAGE_BYTES;
        const uint32_t bS = sB0 + (uint32_t)stg * STAGE_BYTES;
#pragma unroll
        for (int ks = 0; ks < 2; ks++) {
            uint32_t a[4][4];
#pragma unroll
            for (int ma = 0; ma < 4; ma++) {
                int row = wm * 64 + ma * 16 + (lane & 15);
                int ck  = 2 * ks + (lane >> 4);
                uint32_t ad = aS + (uint32_t)(row * PITCH + ck * 8) * 2u;
                asm volatile("ldmatrix.sync.aligned.m8n8.x4.shared.b16 {%0,%1,%2,%3}, [%4];"
                             : "=r"(a[ma][0]), "=r"(a[ma][1]), "=r"(a[ma][2]), "=r"(a[ma][3])
                             : "r"(ad));
            }
            uint32_t b[8][2];
#pragma unroll
            for (int p = 0; p < 4; p++) {
                int row = wn * 64 + p * 16 + (lane & 7) + ((lane >> 4) << 3);
                int ck  = 2 * ks + ((lane >> 3) & 1);
                uint32_t bd = bS + (uint32_t)(row * PITCH + ck * 8) * 2u;
                asm volatile("ldmatrix.sync.aligned.m8n8.x4.shared.b16 {%0,%1,%2,%3}, [%4];"
                             : "=r"(b[2 * p][0]), "=r"(b[2 * p][1]),
                               "=r"(b[2 * p + 1][0]), "=r"(b[2 * p + 1][1])
                             : "r"(bd));
            }
#pragma unroll
            for (int ma = 0; ma < 4; ma++)
#pragma unroll
                for (int na = 0; na < 8; na++) {
                    asm volatile(
                        "mma.sync.aligned.m16n8k16.row.col.f32.bf16.bf16.f32 "
                        "{%0,%1,%2,%3}, {%4,%5,%6,%7}, {%8,%9}, {%0,%1,%2,%3};"
                        : "+f"(c[ma][na][0]), "+f"(c[ma][na][1]),
                          "+f"(c[ma][na][2]), "+f"(c[ma][na][3])
                        : "r"(a[ma][0]), "r"(a[ma][1]), "r"(a[ma][2]), "r"(a[ma][3]),
                          "r"(b[na][0]), "r"(b[na][1]));
                }
        }
    }

    // epilogue: bias + bf16 store + per-row tilemax
    float tmax[8];
#pragma unroll
    for (int i = 0; i < 8; i++) tmax[i] = -1e30f;

#pragma unroll
    for (int ma = 0; ma < 4; ma++) {
#pragma unroll
        for (int na = 0; na < 8; na++) {
            int col = wn * 64 + na * 8 + (lane & 3) * 2;
            float b0 = s_bias[col], b1 = s_bias[col + 1];
            int r0 = m0 + wm * 64 + ma * 16 + (lane >> 2);
            float f0 = c[ma][na][0] + b0, f1 = c[ma][na][1] + b1;
            float f2 = c[ma][na][2] + b0, f3 = c[ma][na][3] + b1;
            tmax[ma * 2]     = fmaxf(tmax[ma * 2],     fmaxf(f0, f1));
            tmax[ma * 2 + 1] = fmaxf(tmax[ma * 2 + 1], fmaxf(f2, f3));
            __nv_bfloat162 v0 = __floats2bfloat162_rn(f0, f1);
            __nv_bfloat162 v1 = __floats2bfloat162_rn(f2, f3);
            *(__nv_bfloat162*)(g_preh + (size_t)r0 * DICT + n0 + col)       = v0;
            *(__nv_bfloat162*)(g_preh + (size_t)(r0 + 8) * DICT + n0 + col) = v1;
        }
    }
#pragma unroll
    for (int i = 0; i < 8; i++) {
        tmax[i] = fmaxf(tmax[i], __shfl_xor_sync(0xffffffffu, tmax[i], 1));
        tmax[i] = fmaxf(tmax[i], __shfl_xor_sync(0xffffffffu, tmax[i], 2));
    }
    __syncthreads();
    if ((lane & 3) == 0) {
#pragma unroll
        for (int ma = 0; ma < 4; ma++) {
            int r = wm * 64 + ma * 16 + (lane >> 2);
            s_tm[r][wn]     = tmax[ma * 2];
            s_tm[r + 8][wn] = tmax[ma * 2 + 1];
        }
    }
    __syncthreads();
    if (tid < 128)
        g_tilemax[(size_t)(m0 + tid) * NTILE + blockIdx.x] =
            fmaxf(s_tm[tid][0], s_tm[tid][1]);
}

// ---------------- K2: topk via tilemax + refined screen + Dot2 ---------------
__device__ __forceinline__ void two_sum(float s, float h, float& t, float& e) {
    t = s + h;
    float z = t - s;
    e = (s - (t - z)) + (h - z);
}

#define TOPK_T 512

__global__ __launch_bounds__(TOPK_T)
void topk_select(const float* __restrict__ x,
                 const float* __restrict__ wenc,
                 const float* __restrict__ benc) {
    __shared__ float s_tmax[NTILE];
    __shared__ float s_m64, s_v64;
    __shared__ int s_ntl, s_ccnt;
    __shared__ short s_tiles[NTILE];
    __shared__ int    s_cidx[CAND_CAP];
    __shared__ float  s_csv[CAND_CAP];
    __shared__ double s_cval[CAND_CAP];
    __shared__ float  s_x[D_MODEL];

    const int row  = blockIdx.x;
    const int tid  = threadIdx.x;
    const int wid  = tid >> 5;
    const int lane = tid & 31;

    if (tid < NTILE) s_tmax[tid] = g_tilemax[(size_t)row * NTILE + tid];
    const float* xr = x + (size_t)row * D_MODEL;
    for (int i = tid; i < D_MODEL; i += TOPK_T) s_x[i] = xr[i];
    if (tid == 0) { s_ntl = 0; s_ccnt = 0; }
    __syncthreads();

    // exact 64th-largest tilemax
    if (tid < NTILE) {
        float v = s_tmax[tid];
        int cnt = 0;
#pragma unroll 4
        for (int j = 0; j < NTILE; j++) {
            float vj = s_tmax[j];
            cnt += (vj > v) || (vj == v && j < tid);
        }
        if (cnt == K_TOP - 1) s_m64 = v;
    }
    __syncthreads();
    const float candLo = s_m64 - MARGIN;
    const float tileLo = candLo - 0.01f;

    if (tid < NTILE && s_tmax[tid] >= tileLo) {
        int p = atomicAdd(&s_ntl, 1);
        s_tiles[p] = (short)tid;
    }
    __syncthreads();
    const int ntl = s_ntl;

    for (int t = wid; t < ntl; t += TOPK_T / 32) {
        int tile = s_tiles[t];
        const uint2* p2 = (const uint2*)(g_preh + (size_t)row * DICT + tile * 128);
        uint2 w = p2[lane];
        int base = tile * 128 + lane * 4;
        float f0 = __uint_as_float(w.x << 16);
        float f1 = __uint_as_float(w.x & 0xFFFF0000u);
        float f2 = __uint_as_float(w.y << 16);
        float f3 = __uint_as_float(w.y & 0xFFFF0000u);
        if (f0 >= candLo) { int p = atomicAdd(&s_ccnt, 1); if (p < CAND_CAP) { s_cidx[p] = base;     s_csv[p] = f0; } }
        if (f1 >= candLo) { int p = atomicAdd(&s_ccnt, 1); if (p < CAND_CAP) { s_cidx[p] = base + 1; s_csv[p] = f1; } }
        if (f2 >= candLo) { int p = atomicAdd(&s_ccnt, 1); if (p < CAND_CAP) { s_cidx[p] = base + 2; s_csv[p] = f2; } }
        if (f3 >= candLo) { int p = atomicAdd(&s_ccnt, 1); if (p < CAND_CAP) { s_cidx[p] = base + 3; s_csv[p] = f3; } }
    }
    __syncthreads();
    const int ccnt = s_ccnt < CAND_CAP ? s_ccnt : CAND_CAP;

    // v64s = 64th-largest screen value among candidates
    for (int cnd = tid; cnd < ccnt; cnd += TOPK_T) {
        float v = s_csv[cnd];
        int cnt = 0;
        for (int j = 0; j < ccnt; j++) {
            float vj = s_csv[j];
            cnt += (vj > v) || (vj == v && j < cnd);
        }
        if (cnt == K_TOP - 1) s_v64 = v;
    }
    __syncthreads();
    const float dotLo = s_v64 - MARGIN;

    for (int cnd = wid; cnd < ccnt; cnd += TOPK_T / 32) {
        if (s_csv[cnd] < dotLo) {
            if (lane == 0) s_cval[cnd] = -1e300;
            continue;
        }
        const int fidx = s_cidx[cnd];
        const float* wr = wenc + (size_t)fidx * D_MODEL;
        float s = 0.f, comp = 0.f;
#pragma unroll
        for (int t = 0; t < 24; t++) {
            int d = t * 32 + lane;
            float a = s_x[d], b = wr[d];
            float h = a * b;
            float r = fmaf(a, b, -h);
            float tnew, e;
            two_sum(s, h, tnew, e);
            s = tnew;
            comp += e + r;
        }
#pragma unroll
        for (int off = 16; off > 0; off >>= 1) {
            float s2 = __shfl_down_sync(0xffffffffu, s, off);
            float c2 = __shfl_down_sync(0xffffffffu, comp, off);
            float tnew, e;
            two_sum(s, s2, tnew, e);
            s = tnew;
            comp += c2 + e;
        }
        if (lane == 0)
            s_cval[cnd] = (double)s + (double)comp + (double)benc[fidx];
    }
    __syncthreads();

    int* irow   = g_idx + (size_t)row * K_TOP;
    float* vrow = g_val + (size_t)row * K_TOP;
    for (int cnd = tid; cnd < ccnt; cnd += TOPK_T) {
        double v = s_cval[cnd];
        int ix = s_cidx[cnd];
        int rank = 0;
        for (int j = 0; j < ccnt; j++) {
            double vj = s_cval[j];
            rank += (vj > v) || (vj == v && s_cidx[j] < ix);
        }
        if (rank < K_TOP) {
            irow[rank] = ix;
            vrow[rank] = fmaxf((float)v, 0.f);
        }
    }
}

// ---------------- K3: sparse decoder + acts scatter --------------------------
__global__ void decode_scatter_kernel(float* __restrict__ recon,
                                      float* __restrict__ acts_out) {
    __shared__ int   sidx[K_TOP];
    __shared__ float sval[K_TOP];
    const int row = blockIdx.x;
    const int tid = threadIdx.x;
    if (tid < K_TOP) {
        int ix  = g_idx[(size_t)row * K_TOP + tid];
        float v = g_val[(size_t)row * K_TOP + tid];
        sidx[tid] = ix;
        sval[tid] = v;
        acts_out[(size_t)row * DICT + ix] = v;
    }
    __syncthreads();

    float a0 = 0.f, a1 = 0.f, a2 = 0.f;
#pragma unroll 8
    for (int j = 0; j < K_TOP; j++) {
        float v = sval[j];
        const float* wr = g_wdt + (size_t)sidx[j] * D_MODEL;
        a0 = fmaf(v, wr[tid],       a0);
        a1 = fmaf(v, wr[tid + 256], a1);
        a2 = fmaf(v, wr[tid + 512], a2);
    }
    float* o = recon + (size_t)row * D_MODEL;
    o[tid]       = a0;
    o[tid + 256] = a1;
    o[tid + 512] = a2;
}

// ---------------- launch ----------------
extern "C" void kernel_launch(void* const* d_in, const int* in_sizes, int n_in,
                              void* d_out, int out_size) {
    const float* x    = (const float*)d_in[0];
    const float* wenc = (const float*)d_in[1];
    const float* benc = (const float*)d_in[2];
    const float* wdec = (const float*)d_in[3];
    (void)in_sizes; (void)n_in; (void)out_size;

    float* out_recon = (float*)d_out;
    float* out_acts  = out_recon + (size_t)B_ROWS * D_MODEL;

    prep_kernel<<<ZBLK + CBLK + TBLK, 256>>>(x, wenc, wdec, out_acts);
    {
        cudaFuncSetAttribute(gemm_enc_mma, cudaFuncAttributeMaxDynamicSharedMemorySize,
                             GEMM_SMEM);
        dim3 grid(DICT / 128, B_ROWS / 128);
        gemm_enc_mma<<<grid, 128, GEMM_SMEM>>>(benc);
    }
    topk_select<<<B_ROWS, TOPK_T>>>(x, wenc, benc);
    decode_scatter_kernel<<<B_ROWS, 256>>>(out_recon, out_acts);
}

// round 16
// speedup vs baseline: 1.1348x; 1.1348x over previous
#include <cuda_runtime.h>
#include <cuda_bf16.h>
#include <stdint.h>

#define B_ROWS   4096
#define D_MODEL  768
#define DICT     24576
#define K_TOP    64
#define CAND_CAP 512
#define MARGIN   0.05f
#define NTILE    (DICT / 128)     // 192

// ---------------- scratch (device globals) ----------------
__device__ __nv_bfloat16 g_xb[(size_t)B_ROWS * D_MODEL];
__device__ __nv_bfloat16 g_wb[(size_t)DICT * D_MODEL];
__device__ __nv_bfloat16 g_preh[(size_t)B_ROWS * DICT];
__device__ float g_tilemax[(size_t)B_ROWS * NTILE];
__device__ float g_wdt[(size_t)DICT * D_MODEL];
__device__ int   g_idx[(size_t)B_ROWS * K_TOP];
__device__ float g_val[(size_t)B_ROWS * K_TOP];

__device__ __forceinline__ uint32_t smem_u32(const void* p) {
    uint32_t a;
    asm("{ .reg .u64 t; cvta.to.shared.u64 t, %1; cvt.u32.u64 %0, t; }" : "=r"(a) : "l"(p));
    return a;
}

// ---------------- K0: fused prep = zero_acts + converts + transpose ----------
#define ZBLK   4096
#define CVT4   ((B_ROWS * D_MODEL + DICT * D_MODEL) / 4)
#define CBLK   ((CVT4 + 255) / 256)
#define TBLK   ((DICT / 32) * (D_MODEL / 32))

__global__ __launch_bounds__(256)
void prep_kernel(const float* __restrict__ x,
                 const float* __restrict__ wenc,
                 const float* __restrict__ wdec,
                 float* __restrict__ acts_out) {
    const int tid = threadIdx.x;
    unsigned b = blockIdx.x;

    if (b < ZBLK) {
        float* arow = acts_out + (size_t)b * DICT;
        float4 z = make_float4(0.f, 0.f, 0.f, 0.f);
#pragma unroll
        for (int i = 0; i < DICT / 4 / 256; i++)
            ((float4*)arow)[tid + i * 256] = z;
        return;
    }
    b -= ZBLK;

    if (b < (unsigned)CBLK) {
        const int nx4 = B_ROWS * D_MODEL / 4;
        int i = b * 256 + tid;
        if (i < nx4) {
            float4 v = ((const float4*)x)[i];
            __nv_bfloat162* o = (__nv_bfloat162*)g_xb;
            o[2 * i]     = __floats2bfloat162_rn(v.x, v.y);
            o[2 * i + 1] = __floats2bfloat162_rn(v.z, v.w);
        } else if (i < CVT4) {
            int j = i - nx4;
            float4 v = ((const float4*)wenc)[j];
            __nv_bfloat162* o = (__nv_bfloat162*)g_wb;
            o[2 * j]     = __floats2bfloat162_rn(v.x, v.y);
            o[2 * j + 1] = __floats2bfloat162_rn(v.z, v.w);
        }
        return;
    }
    b -= CBLK;

    {
        __shared__ float s[32][33];
        const int f0 = (b % (DICT / 32)) * 32;
        const int d0 = (b / (DICT / 32)) * 32;
        const int tx = tid & 31, ty = tid >> 5;
#pragma unroll
        for (int i = 0; i < 4; i++)
            s[ty + i * 8][tx] = wdec[(size_t)(d0 + ty + i * 8) * DICT + f0 + tx];
        __syncthreads();
#pragma unroll
        for (int i = 0; i < 4; i++)
            g_wdt[(size_t)(f0 + ty + i * 8) * D_MODEL + d0 + tx] = s[tx][ty + i * 8];
    }
}

// ---------------- K1: bf16 mma GEMM, 4-stage pipeline, 1 barrier/chunk -------
#define PITCH 40
#define KCH   32
#define NCHUNKS (D_MODEL / KCH)            // 24
#define STAGE_BYTES (128 * PITCH * 2)      // 10240
#define NSTAGE 4
#define GEMM_SMEM (2 * NSTAGE * STAGE_BYTES)   // 81920

__device__ __forceinline__ void cp16(uint32_t saddr, const void* g) {
    asm volatile("cp.async.ca.shared.global [%0], [%1], 16;" :: "r"(saddr), "l"(g));
}

__global__ __launch_bounds__(128, 2)
void gemm_enc_mma(const float* __restrict__ benc) {
    extern __shared__ __align__(128) char dsm[];
    __shared__ float s_bias[128];
    __shared__ float s_tm[128][2];

    const int tid  = threadIdx.x;
    const int wid  = tid >> 5;
    const int lane = tid & 31;
    const int wm   = wid & 1;
    const int wn   = wid >> 1;
    const int m0 = blockIdx.y * 128;
    const int n0 = blockIdx.x * 128;

    if (tid < 128) s_bias[tid] = benc[n0 + tid];

    const __nv_bfloat16* Ag = g_xb + (size_t)m0 * D_MODEL;
    const __nv_bfloat16* Bg = g_wb + (size_t)n0 * D_MODEL;

    const uint32_t sA0 = smem_u32(dsm);
    const uint32_t sB0 = sA0 + NSTAGE * STAGE_BYTES;

    auto issue = [&](int ch, int stg) {
#pragma unroll
        for (int i = 0; i < 4; i++) {
            int seg = tid + (i << 7);
            int r = seg >> 2, c = seg & 3;
            uint32_t so = (uint32_t)stg * STAGE_BYTES + (uint32_t)(r * PITCH + c * 8) * 2u;
            cp16(sA0 + so, Ag + (size_t)r * D_MODEL + ch * KCH + c * 8);
            cp16(sB0 + so, Bg + (size_t)r * D_MODEL + ch * KCH + c * 8);
        }
        asm volatile("cp.async.commit_group;" ::: "memory");
    };

    float c[4][8][4];
#pragma unroll
    for (int i = 0; i < 4; i++)
#pragma unroll
        for (int j = 0; j < 8; j++)
#pragma unroll
            for (int q = 0; q < 4; q++) c[i][j][q] = 0.f;

    issue(0, 0);
    issue(1, 1);
    issue(2, 2);

#pragma unroll 1
    for (int ch = 0; ch < NCHUNKS; ch++) {
        if (ch + 2 < NCHUNKS)
            asm volatile("cp.async.wait_group 2;" ::: "memory");
        else if (ch + 1 < NCHUNKS)
            asm volatile("cp.async.wait_group 1;" ::: "memory");
        else
            asm volatile("cp.async.wait_group 0;" ::: "memory");
        __syncthreads();
        if (ch + 3 < NCHUNKS) issue(ch + 3, (ch + 3) & 3);

        const int stg = ch & 3;
        const uint32_t aS = sA0 + (uint32_t)stg * STAGE_BYTES;
        const uint32_t bS = sB0 + (uint32_t)stg * STAGE_BYTES;
#pragma unroll
        for (int ks = 0; ks < 2; ks++) {
            uint32_t a[4][4];
#pragma unroll
            for (int ma = 0; ma < 4; ma++) {
                int row = wm * 64 + ma * 16 + (lane & 15);
                int ck  = 2 * ks + (lane >> 4);
                uint32_t ad = aS + (uint32_t)(row * PITCH + ck * 8) * 2u;
                asm volatile("ldmatrix.sync.aligned.m8n8.x4.shared.b16 {%0,%1,%2,%3}, [%4];"
                             : "=r"(a[ma][0]), "=r"(a[ma][1]), "=r"(a[ma][2]), "=r"(a[ma][3])
                             : "r"(ad));
            }
            uint32_t b[8][2];
#pragma unroll
            for (int p = 0; p < 4; p++) {
                int row = wn * 64 + p * 16 + (lane & 7) + ((lane >> 4) << 3);
                int ck  = 2 * ks + ((lane >> 3) & 1);
                uint32_t bd = bS + (uint32_t)(row * PITCH + ck * 8) * 2u;
                asm volatile("ldmatrix.sync.aligned.m8n8.x4.shared.b16 {%0,%1,%2,%3}, [%4];"
                             : "=r"(b[2 * p][0]), "=r"(b[2 * p][1]),
                               "=r"(b[2 * p + 1][0]), "=r"(b[2 * p + 1][1])
                             : "r"(bd));
            }
#pragma unroll
            for (int ma = 0; ma < 4; ma++)
#pragma unroll
                for (int na = 0; na < 8; na++) {
                    asm volatile(
                        "mma.sync.aligned.m16n8k16.row.col.f32.bf16.bf16.f32 "
                        "{%0,%1,%2,%3}, {%4,%5,%6,%7}, {%8,%9}, {%0,%1,%2,%3};"
                        : "+f"(c[ma][na][0]), "+f"(c[ma][na][1]),
                          "+f"(c[ma][na][2]), "+f"(c[ma][na][3])
                        : "r"(a[ma][0]), "r"(a[ma][1]), "r"(a[ma][2]), "r"(a[ma][3]),
                          "r"(b[na][0]), "r"(b[na][1]));
                }
        }
    }

    // epilogue: bias + bf16 store + per-row tilemax
    float tmax[8];
#pragma unroll
    for (int i = 0; i < 8; i++) tmax[i] = -1e30f;

#pragma unroll
    for (int ma = 0; ma < 4; ma++) {
#pragma unroll
        for (int na = 0; na < 8; na++) {
            int col = wn * 64 + na * 8 + (lane & 3) * 2;
            float b0 = s_bias[col], b1 = s_bias[col + 1];
            int r0 = m0 + wm * 64 + ma * 16 + (lane >> 2);
            float f0 = c[ma][na][0] + b0, f1 = c[ma][na][1] + b1;
            float f2 = c[ma][na][2] + b0, f3 = c[ma][na][3] + b1;
            tmax[ma * 2]     = fmaxf(tmax[ma * 2],     fmaxf(f0, f1));
            tmax[ma * 2 + 1] = fmaxf(tmax[ma * 2 + 1], fmaxf(f2, f3));
            __nv_bfloat162 v0 = __floats2bfloat162_rn(f0, f1);
            __nv_bfloat162 v1 = __floats2bfloat162_rn(f2, f3);
            *(__nv_bfloat162*)(g_preh + (size_t)r0 * DICT + n0 + col)       = v0;
            *(__nv_bfloat162*)(g_preh + (size_t)(r0 + 8) * DICT + n0 + col) = v1;
        }
    }
#pragma unroll
    for (int i = 0; i < 8; i++) {
        tmax[i] = fmaxf(tmax[i], __shfl_xor_sync(0xffffffffu, tmax[i], 1));
        tmax[i] = fmaxf(tmax[i], __shfl_xor_sync(0xffffffffu, tmax[i], 2));
    }
    __syncthreads();
    if ((lane & 3) == 0) {
#pragma unroll
        for (int ma = 0; ma < 4; ma++) {
            int r = wm * 64 + ma * 16 + (lane >> 2);
            s_tm[r][wn]     = tmax[ma * 2];
            s_tm[r + 8][wn] = tmax[ma * 2 + 1];
        }
    }
    __syncthreads();
    if (tid < 128)
        g_tilemax[(size_t)(m0 + tid) * NTILE + blockIdx.x] =
            fmaxf(s_tm[tid][0], s_tm[tid][1]);
}

// ---------------- K2: topk via tilemax + refined screen + Dot2 ---------------
__device__ __forceinline__ void two_sum(float s, float h, float& t, float& e) {
    t = s + h;
    float z = t - s;
    e = (s - (t - z)) + (h - z);
}

#define TOPK_T 512

__global__ __launch_bounds__(TOPK_T)
void topk_select(const float* __restrict__ x,
                 const float* __restrict__ wenc,
                 const float* __restrict__ benc) {
    __shared__ float s_tmax[NTILE];
    __shared__ float s_m64, s_v64;
    __shared__ int s_ntl, s_ccnt;
    __shared__ short s_tiles[NTILE];
    __shared__ int    s_cidx[CAND_CAP];
    __shared__ float  s_csv[CAND_CAP];
    __shared__ double s_cval[CAND_CAP];
    __shared__ float  s_x[D_MODEL];

    const int row  = blockIdx.x;
    const int tid  = threadIdx.x;
    const int wid  = tid >> 5;
    const int lane = tid & 31;

    if (tid < NTILE) s_tmax[tid] = g_tilemax[(size_t)row * NTILE + tid];
    const float* xr = x + (size_t)row * D_MODEL;
    for (int i = tid; i < D_MODEL; i += TOPK_T) s_x[i] = xr[i];
    if (tid == 0) { s_ntl = 0; s_ccnt = 0; }
    __syncthreads();

    // exact 64th-largest tilemax
    if (tid < NTILE) {
        float v = s_tmax[tid];
        int cnt = 0;
#pragma unroll 4
        for (int j = 0; j < NTILE; j++) {
            float vj = s_tmax[j];
            cnt += (vj > v) || (vj == v && j < tid);
        }
        if (cnt == K_TOP - 1) s_m64 = v;
    }
    __syncthreads();
    const float candLo = s_m64 - MARGIN;
    const float tileLo = candLo - 0.01f;

    if (tid < NTILE && s_tmax[tid] >= tileLo) {
        int p = atomicAdd(&s_ntl, 1);
        s_tiles[p] = (short)tid;
    }
    __syncthreads();
    const int ntl = s_ntl;

    for (int t = wid; t < ntl; t += TOPK_T / 32) {
        int tile = s_tiles[t];
        const uint2* p2 = (const uint2*)(g_preh + (size_t)row * DICT + tile * 128);
        uint2 w = p2[lane];
        int base = tile * 128 + lane * 4;
        float f0 = __uint_as_float(w.x << 16);
        float f1 = __uint_as_float(w.x & 0xFFFF0000u);
        float f2 = __uint_as_float(w.y << 16);
        float f3 = __uint_as_float(w.y & 0xFFFF0000u);
        if (f0 >= candLo) { int p = atomicAdd(&s_ccnt, 1); if (p < CAND_CAP) { s_cidx[p] = base;     s_csv[p] = f0; } }
        if (f1 >= candLo) { int p = atomicAdd(&s_ccnt, 1); if (p < CAND_CAP) { s_cidx[p] = base + 1; s_csv[p] = f1; } }
        if (f2 >= candLo) { int p = atomicAdd(&s_ccnt, 1); if (p < CAND_CAP) { s_cidx[p] = base + 2; s_csv[p] = f2; } }
        if (f3 >= candLo) { int p = atomicAdd(&s_ccnt, 1); if (p < CAND_CAP) { s_cidx[p] = base + 3; s_csv[p] = f3; } }
    }
    __syncthreads();
    const int ccnt = s_ccnt < CAND_CAP ? s_ccnt : CAND_CAP;

    // v64s = 64th-largest screen value among candidates
    for (int cnd = tid; cnd < ccnt; cnd += TOPK_T) {
        float v = s_csv[cnd];
        int cnt = 0;
        for (int j = 0; j < ccnt; j++) {
            float vj = s_csv[j];
            cnt += (vj > v) || (vj == v && j < cnd);
        }
        if (cnt == K_TOP - 1) s_v64 = v;
    }
    __syncthreads();
    const float dotLo = s_v64 - MARGIN;

    for (int cnd = wid; cnd < ccnt; cnd += TOPK_T / 32) {
        if (s_csv[cnd] < dotLo) {
            if (lane == 0) s_cval[cnd] = -1e300;
            continue;
        }
        const int fidx = s_cidx[cnd];
        const float* wr = wenc + (size_t)fidx * D_MODEL;
        float s = 0.f, comp = 0.f;
#pragma unroll
        for (int t = 0; t < 24; t++) {
            int d = t * 32 + lane;
            float a = s_x[d], b = wr[d];
            float h = a * b;
            float r = fmaf(a, b, -h);
            float tnew, e;
            two_sum(s, h, tnew, e);
            s = tnew;
            comp += e + r;
        }
#pragma unroll
        for (int off = 16; off > 0; off >>= 1) {
            float s2 = __shfl_down_sync(0xffffffffu, s, off);
            float c2 = __shfl_down_sync(0xffffffffu, comp, off);
            float tnew, e;
            two_sum(s, s2, tnew, e);
            s = tnew;
            comp += c2 + e;
        }
        if (lane == 0)
            s_cval[cnd] = (double)s + (double)comp + (double)benc[fidx];
    }
    __syncthreads();

    int* irow   = g_idx + (size_t)row * K_TOP;
    float* vrow = g_val + (size_t)row * K_TOP;
    for (int cnd = tid; cnd < ccnt; cnd += TOPK_T) {
        double v = s_cval[cnd];
        int ix = s_cidx[cnd];
        int rank = 0;
        for (int j = 0; j < ccnt; j++) {
            double vj = s_cval[j];
            rank += (vj > v) || (vj == v && s_cidx[j] < ix);
        }
        if (rank < K_TOP) {
            irow[rank] = ix;
            vrow[rank] = fmaxf((float)v, 0.f);
        }
    }
}

// ---------------- K3: sparse decoder + acts scatter --------------------------
__global__ void decode_scatter_kernel(float* __restrict__ recon,
                                      float* __restrict__ acts_out) {
    __shared__ int   sidx[K_TOP];
    __shared__ float sval[K_TOP];
    const int row = blockIdx.x;
    const int tid = threadIdx.x;
    if (tid < K_TOP) {
        int ix  = g_idx[(size_t)row * K_TOP + tid];
        float v = g_val[(size_t)row * K_TOP + tid];
        sidx[tid] = ix;
        sval[tid] = v;
        acts_out[(size_t)row * DICT + ix] = v;
    }
    __syncthreads();

    float a0 = 0.f, a1 = 0.f, a2 = 0.f;
#pragma unroll 8
    for (int j = 0; j < K_TOP; j++) {
        float v = sval[j];
        const float* wr = g_wdt + (size_t)sidx[j] * D_MODEL;
        a0 = fmaf(v, wr[tid],       a0);
        a1 = fmaf(v, wr[tid + 256], a1);
        a2 = fmaf(v, wr[tid + 512], a2);
    }
    float* o = recon + (size_t)row * D_MODEL;
    o[tid]       = a0;
    o[tid + 256] = a1;
    o[tid + 512] = a2;
}

// ---------------- launch ----------------
extern "C" void kernel_launch(void* const* d_in, const int* in_sizes, int n_in,
                              void* d_out, int out_size) {
    const float* x    = (const float*)d_in[0];
    const float* wenc = (const float*)d_in[1];
    const float* benc = (const float*)d_in[2];
    const float* wdec = (const float*)d_in[3];
    (void)in_sizes; (void)n_in; (void)out_size;

    float* out_recon = (float*)d_out;
    float* out_acts  = out_recon + (size_t)B_ROWS * D_MODEL;

    prep_kernel<<<ZBLK + CBLK + TBLK, 256>>>(x, wenc, wdec, out_acts);
    {
        cudaFuncSetAttribute(gemm_enc_mma, cudaFuncAttributeMaxDynamicSharedMemorySize,
                             GEMM_SMEM);
        dim3 grid(DICT / 128, B_ROWS / 128);
        gemm_enc_mma<<<grid, 128, GEMM_SMEM>>>(benc);
    }
    topk_select<<<B_ROWS, TOPK_T>>>(x, wenc, benc);
    decode_scatter_kernel<<<B_ROWS, 256>>>(out_recon, out_acts);
}